// round 5
// baseline (speedup 1.0000x reference)
#include <cuda_runtime.h>
#include <cuda_bf16.h>
#include <cstdint>
#include <cstddef>

// ---------------------------------------------------------------------------
// SAGEConv: gather+mean-agg -> concat -> Linear(1024->512)+ReLU -> BatchNorm
//           -> row L2 normalize.
// GEMM: warp-level mma.sync bf16 (hi/lo split, fp32 accum, 3 passes)
// R5: 4-stage/K16 single-sync pipeline, BN stats fused into GEMM epilogue
// ---------------------------------------------------------------------------

#define DD      512
#define KK      1024
#define NMAX    20000
#define NPAD    20096           // 157 * 128
#define MAXBLK  640

// ------------------------- device scratch (no mallocs) ---------------------
__device__ __align__(16) __nv_bfloat16 g_Ahi[(size_t)NPAD * KK];
__device__ __align__(16) __nv_bfloat16 g_Alo[(size_t)NPAD * KK];
__device__ __align__(16) __nv_bfloat16 g_Whi[(size_t)DD * KK];
__device__ __align__(16) __nv_bfloat16 g_Wlo[(size_t)DD * KK];
__device__ __align__(16) float g_H[(size_t)NMAX * DD];
__device__ float g_psum  [MAXBLK * DD];
__device__ float g_psumsq[MAXBLK * DD];
__device__ __align__(16) float g_scale[DD];
__device__ __align__(16) float g_shift[DD];
__device__ int   g_idx_is64;

// ------------------------- helpers -----------------------------------------
__device__ __forceinline__ uint32_t smem_u32(const void* p) {
    uint32_t a;
    asm("{ .reg .u64 t; cvta.to.shared.u64 t, %1; cvt.u32.u64 %0, t; }"
        : "=r"(a) : "l"(p));
    return a;
}
__device__ __forceinline__ void cpasync16(uint32_t dst, const void* src) {
    asm volatile("cp.async.cg.shared.global [%0], [%1], 16;"
                 :: "r"(dst), "l"(src) : "memory");
}
__device__ __forceinline__ void cp_commit() {
    asm volatile("cp.async.commit_group;" ::: "memory");
}
__device__ __forceinline__ void ldsm4(uint32_t& r0, uint32_t& r1,
                                      uint32_t& r2, uint32_t& r3, uint32_t a) {
    asm volatile("ldmatrix.sync.aligned.m8n8.x4.shared.b16 {%0,%1,%2,%3}, [%4];"
                 : "=r"(r0), "=r"(r1), "=r"(r2), "=r"(r3) : "r"(a));
}
__device__ __forceinline__ void mma16816(float* d, const uint32_t* a,
                                         const uint32_t* b) {
    asm volatile(
        "mma.sync.aligned.m16n8k16.row.col.f32.bf16.bf16.f32 "
        "{%0,%1,%2,%3}, {%4,%5,%6,%7}, {%8,%9}, {%0,%1,%2,%3};"
        : "+f"(d[0]), "+f"(d[1]), "+f"(d[2]), "+f"(d[3])
        : "r"(a[0]), "r"(a[1]), "r"(a[2]), "r"(a[3]), "r"(b[0]), "r"(b[1]));
}

// bf16 hi/lo split of two floats, packed as bf16x2 words (x0 in low half)
__device__ __forceinline__ void split2(float x0, float x1, uint32_t& hi2, uint32_t& lo2) {
    float h0 = __bfloat162float(__float2bfloat16_rn(x0));
    float h1 = __bfloat162float(__float2bfloat16_rn(x1));
    float l0 = x0 - h0, l1 = x1 - h1;
    asm("cvt.rn.bf16x2.f32 %0, %1, %2;" : "=r"(hi2) : "f"(h1), "f"(h0));
    asm("cvt.rn.bf16x2.f32 %0, %1, %2;" : "=r"(lo2) : "f"(l1), "f"(l0));
}

// ------------------------- index dtype detection ---------------------------
__global__ void detect_idx_kernel(const unsigned int* __restrict__ p, int n) {
    __shared__ unsigned int red[256];
    unsigned int acc = 0;
    for (int i = threadIdx.x; i < n; i += blockDim.x)
        if (i & 1) acc |= p[i];
    red[threadIdx.x] = acc;
    __syncthreads();
    for (int s = 128; s > 0; s >>= 1) {
        if (threadIdx.x < s) red[threadIdx.x] |= red[threadIdx.x + s];
        __syncthreads();
    }
    if (threadIdx.x == 0) g_idx_is64 = (red[0] == 0u) ? 1 : 0;
}
__device__ __forceinline__ long long load_idx(const void* p, size_t i, int is64) {
    if (is64) return ((const long long*)p)[i];
    return (long long)((const int*)p)[i];
}

// ------------------------- kernel 1: gather + mean agg -> bf16 hi/lo -------
__global__ __launch_bounds__(128)
void agg_kernel(const float4* __restrict__ feat4,
                const void* __restrict__ self_idx,
                const void* __restrict__ neigh_idx,
                int N, int S) {
    const int n = blockIdx.x;
    const int t = threadIdx.x;
    __shared__ long long sidx[40];
    const int is64 = g_idx_is64;
    if (t == 0) sidx[S] = load_idx(self_idx, n, is64);
    if (t < S)  sidx[t] = load_idx(neigh_idx, (size_t)n * S + t, is64);
    __syncthreads();

    uint2* Ah = reinterpret_cast<uint2*>(g_Ahi);
    uint2* Al = reinterpret_cast<uint2*>(g_Alo);

    {   // self half
        float4 v = feat4[(size_t)sidx[S] * 128 + t];
        uint2 hi, lo;
        split2(v.x, v.y, hi.x, lo.x);
        split2(v.z, v.w, hi.y, lo.y);
        Ah[(size_t)n * 256 + t] = hi;
        Al[(size_t)n * 256 + t] = lo;
    }
    float4 acc = make_float4(0.f, 0.f, 0.f, 0.f);
    for (int s = 0; s < S; ++s) {
        float4 v = feat4[(size_t)sidx[s] * 128 + t];
        acc.x += v.x; acc.y += v.y; acc.z += v.z; acc.w += v.w;
    }
    const float inv = 1.0f / (float)S;
    acc.x *= inv; acc.y *= inv; acc.z *= inv; acc.w *= inv;
    uint2 hi, lo;
    split2(acc.x, acc.y, hi.x, lo.x);
    split2(acc.z, acc.w, hi.y, lo.y);
    Ah[(size_t)n * 256 + 128 + t] = hi;
    Al[(size_t)n * 256 + 128 + t] = lo;
}

// ------------------------- kernel 1b: split W to bf16 hi/lo ----------------
__global__ __launch_bounds__(256)
void wconv_kernel(const float* __restrict__ W) {
    const int i = blockIdx.x * 256 + threadIdx.x;
    const float4 v = *(const float4*)(W + (size_t)i * 4);
    uint2 hi, lo;
    split2(v.x, v.y, hi.x, lo.x);
    split2(v.z, v.w, hi.y, lo.y);
    ((uint2*)g_Whi)[i] = hi;
    ((uint2*)g_Wlo)[i] = lo;
}

// ------------------------- kernel 2: HMMA GEMM + bias + ReLU + BN partials -
// H[128x128 tile] = A[128,1024] * W[128-slice,1024]^T, 3-pass hi/lo.
// 4-stage pipeline, K=16 per chunk, one __syncthreads per chunk.
// smem per stage: 4 variants x [128 rows x 16 halfs], row stride 48B
// (16B-aligned rows, banks 0,3,6,1,4,7,2,5 -> conflict-free ldmatrix).
#define SASTRIDE 48                       // bytes per smem row
#define VARB     6144                     // 128*48 per variant
#define STAGEB   (4 * VARB)               // 24576
#define NSTAGE   4
#define HDRB     1024
#define GEMM_SMEM (HDRB + NSTAGE * STAGEB)   // 99328 -> 2 CTAs/SM

__global__ __launch_bounds__(256, 2)
void gemm_tc_kernel(const float* __restrict__ bias, int M) {
    extern __shared__ char smem[];
    const uint32_t sb = smem_u32(smem);
    const int tid  = threadIdx.x;
    const int wid  = tid >> 5;
    const int lane = tid & 31;
    const int wm   = wid >> 2;            // 0..1  (64 rows each)
    const int wn   = wid & 3;             // 0..3  (32 cols each)
    const int m0 = blockIdx.y * 128;
    const int n0 = blockIdx.x * 128;

    float* bsm = (float*)smem;            // bias cache [128]
    if (tid < 128) bsm[tid] = bias[n0 + tid];

    // per-lane ldmatrix offsets (bytes)
    const uint32_t aOff = (uint32_t)((lane & 15) * SASTRIDE + (lane >> 4) * 16);
    const uint32_t bOff = (uint32_t)(((lane & 7) + ((lane >> 4) << 3)) * SASTRIDE
                                     + (((lane >> 3) & 1) << 4));

    const char* pAhi = (const char*)g_Ahi;
    const char* pAlo = (const char*)g_Alo;
    const char* pWhi = (const char*)g_Whi;
    const char* pWlo = (const char*)g_Wlo;

    // one 16B transfer per variant per thread per chunk
    const int lr = tid >> 1;              // 0..127  row
    const int lc = tid & 1;               // 0..1    16B column
    auto load_chunk = [&](int stage, int kc) {
        const uint32_t dst = sb + HDRB + stage * STAGEB
                           + (uint32_t)(lr * SASTRIDE + lc * 16);
        const size_t sa  = ((size_t)(m0 + lr) << 11) + (size_t)(kc * 32 + lc * 16);
        const size_t sbo = ((size_t)(n0 + lr) << 11) + (size_t)(kc * 32 + lc * 16);
        cpasync16(dst,            pAhi + sa);
        cpasync16(dst + VARB,     pAlo + sa);
        cpasync16(dst + 2 * VARB, pWhi + sbo);
        cpasync16(dst + 3 * VARB, pWlo + sbo);
        cp_commit();
    };

    float acc[4][4][4];
    #pragma unroll
    for (int i = 0; i < 4; ++i)
        #pragma unroll
        for (int j = 0; j < 4; ++j)
            #pragma unroll
            for (int q = 0; q < 4; ++q) acc[i][j][q] = 0.f;

    load_chunk(0, 0);
    load_chunk(1, 1);
    load_chunk(2, 2);

    const int NKC = KK / 16;              // 64 chunks
    for (int kc = 0; kc < NKC; ++kc) {
        asm volatile("cp.async.wait_group 2;" ::: "memory");
        __syncthreads();

        // refill the stage consumed last iteration (safe after the sync)
        if (kc + 3 < NKC) load_chunk((kc + 3) & 3, kc + 3);
        else              cp_commit();    // keep group count uniform

        const uint32_t st = sb + HDRB + (kc & 3) * STAGEB;
        const uint32_t bufAhi = st;
        const uint32_t bufAlo = st + VARB;
        const uint32_t bufBhi = st + 2 * VARB;
        const uint32_t bufBlo = st + 3 * VARB;

        uint32_t ah[4][4], al[4][4], bh[2][4], bl[2][4];
        #pragma unroll
        for (int j2 = 0; j2 < 2; ++j2) {
            const uint32_t ro = (uint32_t)((wn * 32 + j2 * 16) * SASTRIDE);
            ldsm4(bh[j2][0], bh[j2][1], bh[j2][2], bh[j2][3], bufBhi + ro + bOff);
            ldsm4(bl[j2][0], bl[j2][1], bl[j2][2], bl[j2][3], bufBlo + ro + bOff);
        }
        #pragma unroll
        for (int im = 0; im < 4; ++im) {
            const uint32_t ro = (uint32_t)((wm * 64 + im * 16) * SASTRIDE);
            ldsm4(ah[im][0], ah[im][1], ah[im][2], ah[im][3], bufAhi + ro + aOff);
            ldsm4(al[im][0], al[im][1], al[im][2], al[im][3], bufAlo + ro + aOff);
        }
        #pragma unroll
        for (int im = 0; im < 4; ++im)
            #pragma unroll
            for (int jn = 0; jn < 4; ++jn) {
                const uint32_t* ph = &bh[jn >> 1][(jn & 1) * 2];
                const uint32_t* pl = &bl[jn >> 1][(jn & 1) * 2];
                mma16816(acc[im][jn], ah[im], ph);   // hi*hi
                mma16816(acc[im][jn], ah[im], pl);   // hi*lo
                mma16816(acc[im][jn], al[im], ph);   // lo*hi
            }
    }

    // ---- epilogue: bias + relu -> g_H, plus BN partial sums (fused) ----
    __syncthreads();                       // done with pipeline smem; reuse it
    float* psum = (float*)(smem + HDRB);            // [128 cols][16 slots]
    float* psq  = (float*)(smem + HDRB + 8192);
    const int g    = lane >> 2;
    const int tq   = lane & 3;
    const int slot = wm * 8 + g;

    #pragma unroll
    for (int jn = 0; jn < 4; ++jn) {
        const int colL = wn * 32 + jn * 8 + tq * 2;   // within 128-tile
        const float b0 = bsm[colL], b1 = bsm[colL + 1];
        float s0 = 0.f, s1 = 0.f, q0 = 0.f, q1 = 0.f;
        #pragma unroll
        for (int im = 0; im < 4; ++im) {
            const int row0 = m0 + wm * 64 + im * 16 + g;
            float v0 = acc[im][jn][0] + b0;
            float v1 = acc[im][jn][1] + b1;
            float v2 = acc[im][jn][2] + b0;
            float v3 = acc[im][jn][3] + b1;
            v0 = v0 > 0.f ? v0 : 0.f;
            v1 = v1 > 0.f ? v1 : 0.f;
            v2 = v2 > 0.f ? v2 : 0.f;
            v3 = v3 > 0.f ? v3 : 0.f;
            const int col = n0 + colL;
            if (row0 < M) {
                *(float2*)(g_H + (size_t)row0 * DD + col) = make_float2(v0, v1);
                s0 += v0; s1 += v1; q0 += v0 * v0; q1 += v1 * v1;
            }
            if (row0 + 8 < M) {
                *(float2*)(g_H + (size_t)(row0 + 8) * DD + col) = make_float2(v2, v3);
                s0 += v2; s1 += v3; q0 += v2 * v2; q1 += v3 * v3;
            }
        }
        psum[colL * 16 + slot]       = s0;
        psum[(colL + 1) * 16 + slot] = s1;
        psq [colL * 16 + slot]       = q0;
        psq [(colL + 1) * 16 + slot] = q1;
    }
    __syncthreads();

    // deterministic slot reduction: 256 threads -> 128 cols x {sum, sumsq}
    {
        const int col = tid & 127;
        const float* src = (tid & 128) ? psq : psum;
        float s = 0.f;
        #pragma unroll
        for (int k = 0; k < 16; ++k) s += src[col * 16 + k];
        float* dstg = (tid & 128) ? g_psumsq : g_psum;
        dstg[blockIdx.y * DD + n0 + col] = s;
    }
}

// ------------------------- BN finalize -------------------------------------
__global__ __launch_bounds__(256)
void finalize_stats(const float* __restrict__ gamma,
                    const float* __restrict__ beta, int M, int nblk) {
    const int col  = blockIdx.x * 8 + (threadIdx.x >> 5);
    const int lane = threadIdx.x & 31;
    float s = 0.f, q = 0.f;
    for (int i = lane; i < nblk; i += 32) {
        s += g_psum  [i * DD + col];
        q += g_psumsq[i * DD + col];
    }
    #pragma unroll
    for (int o = 16; o > 0; o >>= 1) {
        s += __shfl_xor_sync(0xffffffffu, s, o);
        q += __shfl_xor_sync(0xffffffffu, q, o);
    }
    if (lane == 0) {
        const float invM = 1.0f / (float)M;
        const float mean = s * invM;
        const float var  = q * invM - mean * mean;
        const float rstd = rsqrtf(var + 1e-5f);
        const float sc = rstd * gamma[col];
        g_scale[col] = sc;
        g_shift[col] = beta[col] - mean * sc;
    }
}

// ------------------------- kernel 4: BN apply + row L2 normalize -----------
__global__ __launch_bounds__(128)
void bn_l2_kernel(float4* __restrict__ out4, int M) {
    const int n = blockIdx.x;
    const int t = threadIdx.x;
    const float4* H4  = reinterpret_cast<const float4*>(g_H);
    const float4* sc4 = reinterpret_cast<const float4*>(g_scale);
    const float4* sh4 = reinterpret_cast<const float4*>(g_shift);

    float4 h  = H4[(size_t)n * 128 + t];
    float4 sc = sc4[t];
    float4 sh = sh4[t];
    float4 y;
    y.x = h.x * sc.x + sh.x;
    y.y = h.y * sc.y + sh.y;
    y.z = h.z * sc.z + sh.z;
    y.w = h.w * sc.w + sh.w;

    float ss = y.x * y.x + y.y * y.y + y.z * y.z + y.w * y.w;
    #pragma unroll
    for (int o = 16; o > 0; o >>= 1)
        ss += __shfl_xor_sync(0xffffffffu, ss, o);

    __shared__ float ws[4];
    if ((t & 31) == 0) ws[t >> 5] = ss;
    __syncthreads();
    const float tot = ws[0] + ws[1] + ws[2] + ws[3];
    const float inv = 1.0f / (sqrtf(tot) + 1e-6f);

    y.x *= inv; y.y *= inv; y.z *= inv; y.w *= inv;
    out4[(size_t)n * 128 + t] = y;
}

// ------------------------- launcher ----------------------------------------
extern "C" void kernel_launch(void* const* d_in, const int* in_sizes, int n_in,
                              void* d_out, int out_size) {
    const float* features = (const float*)d_in[0];
    const float* W        = (const float*)d_in[1];
    const float* b        = (const float*)d_in[2];
    const float* gamma    = (const float*)d_in[3];
    const float* beta     = (const float*)d_in[4];
    const void*  self_idx = d_in[5];
    const void*  neigh_idx= d_in[6];

    const int N = in_sizes[5];
    const int S = in_sizes[6] / N;

    cudaFuncSetAttribute(gemm_tc_kernel,
                         cudaFuncAttributeMaxDynamicSharedMemorySize, GEMM_SMEM);

    detect_idx_kernel<<<1, 256>>>((const unsigned int*)self_idx, N);
    wconv_kernel<<<(DD * KK / 4) / 256, 256>>>(W);
    agg_kernel<<<N, 128>>>((const float4*)features, self_idx, neigh_idx, N, S);

    dim3 ggrid(DD / 128, (N + 127) / 128);
    gemm_tc_kernel<<<ggrid, 256, GEMM_SMEM>>>(b, N);

    const int nblk = (N + 127) / 128;     // one partial per GEMM row-stripe
    finalize_stats<<<64, 256>>>(gamma, beta, N, nblk);

    bn_l2_kernel<<<N, 128>>>((float4*)d_out, N);
}

// round 6
// speedup vs baseline: 1.3530x; 1.3530x over previous
#include <cuda_runtime.h>
#include <cuda_fp16.h>
#include <cstdint>
#include <cstddef>

// ---------------------------------------------------------------------------
// SAGEConv: gather+mean-agg -> concat -> Linear(1024->512)+ReLU -> BatchNorm
//           -> row L2 normalize.
// GEMM: mma.sync fp16, A single-precision fp16, W split hi/lo (2 passes),
//       fp32 accumulate. BN stats fused into GEMM epilogue.
// ---------------------------------------------------------------------------

#define DD      512
#define KK      1024
#define NMAX    20000
#define NPAD    20096           // 157 * 128
#define MAXBLK  640

// ------------------------- device scratch (no mallocs) ---------------------
__device__ __align__(16) __half g_A  [(size_t)NPAD * KK];   // ~41 MB
__device__ __align__(16) __half g_Whi[(size_t)DD * KK];
__device__ __align__(16) __half g_Wlo[(size_t)DD * KK];
__device__ __align__(16) float g_H[(size_t)NMAX * DD];      // 41 MB
__device__ float g_psum  [MAXBLK * DD];
__device__ float g_psumsq[MAXBLK * DD];
__device__ __align__(16) float g_scale[DD];
__device__ __align__(16) float g_shift[DD];
__device__ int   g_idx_is64;

// ------------------------- helpers -----------------------------------------
__device__ __forceinline__ uint32_t smem_u32(const void* p) {
    uint32_t a;
    asm("{ .reg .u64 t; cvta.to.shared.u64 t, %1; cvt.u32.u64 %0, t; }"
        : "=r"(a) : "l"(p));
    return a;
}
__device__ __forceinline__ void cpasync16(uint32_t dst, const void* src) {
    asm volatile("cp.async.cg.shared.global [%0], [%1], 16;"
                 :: "r"(dst), "l"(src) : "memory");
}
__device__ __forceinline__ void cp_commit() {
    asm volatile("cp.async.commit_group;" ::: "memory");
}
__device__ __forceinline__ void ldsm4(uint32_t& r0, uint32_t& r1,
                                      uint32_t& r2, uint32_t& r3, uint32_t a) {
    asm volatile("ldmatrix.sync.aligned.m8n8.x4.shared.b16 {%0,%1,%2,%3}, [%4];"
                 : "=r"(r0), "=r"(r1), "=r"(r2), "=r"(r3) : "r"(a));
}
__device__ __forceinline__ void mma16816(float* d, const uint32_t* a,
                                         const uint32_t* b) {
    asm volatile(
        "mma.sync.aligned.m16n8k16.row.col.f32.f16.f16.f32 "
        "{%0,%1,%2,%3}, {%4,%5,%6,%7}, {%8,%9}, {%0,%1,%2,%3};"
        : "+f"(d[0]), "+f"(d[1]), "+f"(d[2]), "+f"(d[3])
        : "r"(a[0]), "r"(a[1]), "r"(a[2]), "r"(a[3]), "r"(b[0]), "r"(b[1]));
}

// pack two floats to f16x2 (x0 in low half)
__device__ __forceinline__ uint32_t packh2(float x0, float x1) {
    __half2 h = __floats2half2_rn(x0, x1);
    return *reinterpret_cast<uint32_t*>(&h);
}

// ------------------------- index dtype detection ---------------------------
__global__ void detect_idx_kernel(const unsigned int* __restrict__ p, int n) {
    __shared__ unsigned int red[256];
    unsigned int acc = 0;
    for (int i = threadIdx.x; i < n; i += blockDim.x)
        if (i & 1) acc |= p[i];
    red[threadIdx.x] = acc;
    __syncthreads();
    for (int s = 128; s > 0; s >>= 1) {
        if (threadIdx.x < s) red[threadIdx.x] |= red[threadIdx.x + s];
        __syncthreads();
    }
    if (threadIdx.x == 0) g_idx_is64 = (red[0] == 0u) ? 1 : 0;
}
__device__ __forceinline__ long long load_idx(const void* p, size_t i, int is64) {
    if (is64) return ((const long long*)p)[i];
    return (long long)((const int*)p)[i];
}

// ------------------------- kernel 1: gather + mean agg -> fp16 -------------
__global__ __launch_bounds__(128)
void agg_kernel(const float4* __restrict__ feat4,
                const void* __restrict__ self_idx,
                const void* __restrict__ neigh_idx,
                int N, int S) {
    const int n = blockIdx.x;
    const int t = threadIdx.x;          // owns halfs 4t..4t+3 of each 512-half
    __shared__ long long sidx[40];
    const int is64 = g_idx_is64;
    if (t == 0) sidx[S] = load_idx(self_idx, n, is64);
    if (t < S)  sidx[t] = load_idx(neigh_idx, (size_t)n * S + t, is64);
    __syncthreads();

    uint2* A2 = reinterpret_cast<uint2*>(g_A);

    {   // self half (cols 0..511)
        float4 v = feat4[(size_t)sidx[S] * 128 + t];
        uint2 o;
        o.x = packh2(v.x, v.y);
        o.y = packh2(v.z, v.w);
        A2[(size_t)n * 256 + t] = o;
    }
    float4 acc = make_float4(0.f, 0.f, 0.f, 0.f);
    for (int s = 0; s < S; ++s) {
        float4 v = feat4[(size_t)sidx[s] * 128 + t];
        acc.x += v.x; acc.y += v.y; acc.z += v.z; acc.w += v.w;
    }
    const float inv = 1.0f / (float)S;
    uint2 o;
    o.x = packh2(acc.x * inv, acc.y * inv);
    o.y = packh2(acc.z * inv, acc.w * inv);
    A2[(size_t)n * 256 + 128 + t] = o;
}

// ------------------------- kernel 1b: split W to fp16 hi/lo ----------------
__global__ __launch_bounds__(256)
void wconv_kernel(const float* __restrict__ W) {
    const int i = blockIdx.x * 256 + threadIdx.x;    // over DD*KK/4
    const float4 v = *(const float4*)(W + (size_t)i * 4);
    float h0 = __half2float(__float2half_rn(v.x));
    float h1 = __half2float(__float2half_rn(v.y));
    float h2 = __half2float(__float2half_rn(v.z));
    float h3 = __half2float(__float2half_rn(v.w));
    uint2 hi, lo;
    hi.x = packh2(h0, h1);       hi.y = packh2(h2, h3);
    lo.x = packh2(v.x - h0, v.y - h1);
    lo.y = packh2(v.z - h2, v.w - h3);
    ((uint2*)g_Whi)[i] = hi;
    ((uint2*)g_Wlo)[i] = lo;
}

// ------------------------- kernel 2: HMMA GEMM + bias + ReLU + BN partials -
// H[128x128 tile] = A[128,1024] * W[128-slice,1024]^T, 2-pass (W hi/lo).
// 3 variants (A, Whi, Wlo) of [128 rows][32 k] fp16, row stride 80B.
// 3 stages, K=32 per chunk, ONE __syncthreads per chunk.
#define SASTRIDE 80                       // bytes per smem row
#define VARB     10240                    // 128*80 per variant
#define STAGEB   (3 * VARB)               // 30720
#define NSTAGE   3
#define HDRB     1024
#define GEMM_SMEM (HDRB + NSTAGE * STAGEB)   // 93184 -> 2 CTAs/SM

__global__ __launch_bounds__(256, 2)
void gemm_tc_kernel(const float* __restrict__ bias, int M) {
    extern __shared__ char smem[];
    const uint32_t sb = smem_u32(smem);
    const int tid  = threadIdx.x;
    const int wid  = tid >> 5;
    const int lane = tid & 31;
    const int wm   = wid >> 2;            // 0..1  (64 rows each)
    const int wn   = wid & 3;             // 0..3  (32 cols each)
    const int m0 = blockIdx.y * 128;
    const int n0 = blockIdx.x * 128;

    float* bsm = (float*)smem;            // bias cache [128]
    if (tid < 128) bsm[tid] = bias[n0 + tid];

    const uint32_t aOff = (uint32_t)((lane & 15) * SASTRIDE + (lane >> 4) * 16);
    const uint32_t bOff = (uint32_t)(((lane & 7) + ((lane >> 4) << 3)) * SASTRIDE
                                     + (((lane >> 3) & 1) << 4));

    const char* pA   = (const char*)g_A;
    const char* pWhi = (const char*)g_Whi;
    const char* pWlo = (const char*)g_Wlo;

    auto load_chunk = [&](int stage, int kc) {
        const uint32_t base = sb + HDRB + stage * STAGEB;
        #pragma unroll
        for (int i = 0; i < 2; ++i) {
            const int idx = tid + (i << 8);
            const int r = idx >> 2, c = idx & 3;
            const uint32_t dst = base + (uint32_t)(r * SASTRIDE + c * 16);
            const size_t sa  = ((size_t)(m0 + r) << 11) + (size_t)(kc * 64 + c * 16);
            const size_t sbo = ((size_t)(n0 + r) << 11) + (size_t)(kc * 64 + c * 16);
            cpasync16(dst,            pA   + sa);
            cpasync16(dst + VARB,     pWhi + sbo);
            cpasync16(dst + 2 * VARB, pWlo + sbo);
        }
        cp_commit();
    };

    float acc[4][4][4];
    #pragma unroll
    for (int i = 0; i < 4; ++i)
        #pragma unroll
        for (int j = 0; j < 4; ++j)
            #pragma unroll
            for (int q = 0; q < 4; ++q) acc[i][j][q] = 0.f;

    load_chunk(0, 0);
    load_chunk(1, 1);

    const int NKC = KK / 32;              // 32 chunks
    for (int kc = 0; kc < NKC; ++kc) {
        asm volatile("cp.async.wait_group 1;" ::: "memory");
        __syncthreads();

        // refill stage consumed last iteration
        if (kc + 2 < NKC) load_chunk((kc + 2) % 3, kc + 2);
        else              cp_commit();

        const uint32_t st = sb + HDRB + (kc % 3) * STAGEB;
        const uint32_t bufA  = st;
        const uint32_t bufBh = st + VARB;
        const uint32_t bufBl = st + 2 * VARB;

        #pragma unroll
        for (int k16 = 0; k16 < 2; ++k16) {
            const uint32_t kb = (uint32_t)(k16 * 32);
            uint32_t a[4][4], bh[2][4], bl[2][4];
            #pragma unroll
            for (int j2 = 0; j2 < 2; ++j2) {
                const uint32_t ro = (uint32_t)((wn * 32 + j2 * 16) * SASTRIDE) + kb;
                ldsm4(bh[j2][0], bh[j2][1], bh[j2][2], bh[j2][3], bufBh + ro + bOff);
                ldsm4(bl[j2][0], bl[j2][1], bl[j2][2], bl[j2][3], bufBl + ro + bOff);
            }
            #pragma unroll
            for (int im = 0; im < 4; ++im) {
                const uint32_t ro = (uint32_t)((wm * 64 + im * 16) * SASTRIDE) + kb;
                ldsm4(a[im][0], a[im][1], a[im][2], a[im][3], bufA + ro + aOff);
            }
            #pragma unroll
            for (int im = 0; im < 4; ++im)
                #pragma unroll
                for (int jn = 0; jn < 4; ++jn) {
                    const uint32_t* ph = &bh[jn >> 1][(jn & 1) * 2];
                    const uint32_t* pl = &bl[jn >> 1][(jn & 1) * 2];
                    mma16816(acc[im][jn], a[im], ph);   // A * W_hi
                    mma16816(acc[im][jn], a[im], pl);   // A * W_lo
                }
        }
    }

    // ---- epilogue: bias + relu -> g_H, plus BN partial sums (fused) ----
    __syncthreads();                       // done with pipeline smem; reuse it
    float* psum = (float*)(smem + HDRB);            // [128 cols][16 slots]
    float* psq  = (float*)(smem + HDRB + 8192);
    const int g    = lane >> 2;
    const int tq   = lane & 3;
    const int slot = wm * 8 + g;

    #pragma unroll
    for (int jn = 0; jn < 4; ++jn) {
        const int colL = wn * 32 + jn * 8 + tq * 2;
        const float b0 = bsm[colL], b1 = bsm[colL + 1];
        float s0 = 0.f, s1 = 0.f, q0 = 0.f, q1 = 0.f;
        #pragma unroll
        for (int im = 0; im < 4; ++im) {
            const int row0 = m0 + wm * 64 + im * 16 + g;
            float v0 = acc[im][jn][0] + b0;
            float v1 = acc[im][jn][1] + b1;
            float v2 = acc[im][jn][2] + b0;
            float v3 = acc[im][jn][3] + b1;
            v0 = v0 > 0.f ? v0 : 0.f;
            v1 = v1 > 0.f ? v1 : 0.f;
            v2 = v2 > 0.f ? v2 : 0.f;
            v3 = v3 > 0.f ? v3 : 0.f;
            const int col = n0 + colL;
            if (row0 < M) {
                *(float2*)(g_H + (size_t)row0 * DD + col) = make_float2(v0, v1);
                s0 += v0; s1 += v1; q0 += v0 * v0; q1 += v1 * v1;
            }
            if (row0 + 8 < M) {
                *(float2*)(g_H + (size_t)(row0 + 8) * DD + col) = make_float2(v2, v3);
                s0 += v2; s1 += v3; q0 += v2 * v2; q1 += v3 * v3;
            }
        }
        psum[colL * 16 + slot]       = s0;
        psum[(colL + 1) * 16 + slot] = s1;
        psq [colL * 16 + slot]       = q0;
        psq [(colL + 1) * 16 + slot] = q1;
    }
    __syncthreads();

    // deterministic slot reduction: 256 threads -> 128 cols x {sum, sumsq}
    {
        const int col = tid & 127;
        const float* src = (tid & 128) ? psq : psum;
        float s = 0.f;
        #pragma unroll
        for (int k = 0; k < 16; ++k) s += src[col * 16 + k];
        float* dstg = (tid & 128) ? g_psumsq : g_psum;
        dstg[blockIdx.y * DD + n0 + col] = s;
    }
}

// ------------------------- BN finalize -------------------------------------
__global__ __launch_bounds__(256)
void finalize_stats(const float* __restrict__ gamma,
                    const float* __restrict__ beta, int M, int nblk) {
    const int col  = blockIdx.x * 8 + (threadIdx.x >> 5);
    const int lane = threadIdx.x & 31;
    float s = 0.f, q = 0.f;
    for (int i = lane; i < nblk; i += 32) {
        s += g_psum  [i * DD + col];
        q += g_psumsq[i * DD + col];
    }
    #pragma unroll
    for (int o = 16; o > 0; o >>= 1) {
        s += __shfl_xor_sync(0xffffffffu, s, o);
        q += __shfl_xor_sync(0xffffffffu, q, o);
    }
    if (lane == 0) {
        const float invM = 1.0f / (float)M;
        const float mean = s * invM;
        const float var  = q * invM - mean * mean;
        const float rstd = rsqrtf(var + 1e-5f);
        const float sc = rstd * gamma[col];
        g_scale[col] = sc;
        g_shift[col] = beta[col] - mean * sc;
    }
}

// ------------------------- kernel 4: BN apply + row L2 normalize -----------
__global__ __launch_bounds__(128)
void bn_l2_kernel(float4* __restrict__ out4, int M) {
    const int n = blockIdx.x;
    const int t = threadIdx.x;
    const float4* H4  = reinterpret_cast<const float4*>(g_H);
    const float4* sc4 = reinterpret_cast<const float4*>(g_scale);
    const float4* sh4 = reinterpret_cast<const float4*>(g_shift);

    float4 h  = H4[(size_t)n * 128 + t];
    float4 sc = sc4[t];
    float4 sh = sh4[t];
    float4 y;
    y.x = h.x * sc.x + sh.x;
    y.y = h.y * sc.y + sh.y;
    y.z = h.z * sc.z + sh.z;
    y.w = h.w * sc.w + sh.w;

    float ss = y.x * y.x + y.y * y.y + y.z * y.z + y.w * y.w;
    #pragma unroll
    for (int o = 16; o > 0; o >>= 1)
        ss += __shfl_xor_sync(0xffffffffu, ss, o);

    __shared__ float ws[4];
    if ((t & 31) == 0) ws[t >> 5] = ss;
    __syncthreads();
    const float tot = ws[0] + ws[1] + ws[2] + ws[3];
    const float inv = 1.0f / (sqrtf(tot) + 1e-6f);

    y.x *= inv; y.y *= inv; y.z *= inv; y.w *= inv;
    out4[(size_t)n * 128 + t] = y;
}

// ------------------------- launcher ----------------------------------------
extern "C" void kernel_launch(void* const* d_in, const int* in_sizes, int n_in,
                              void* d_out, int out_size) {
    const float* features = (const float*)d_in[0];
    const float* W        = (const float*)d_in[1];
    const float* b        = (const float*)d_in[2];
    const float* gamma    = (const float*)d_in[3];
    const float* beta     = (const float*)d_in[4];
    const void*  self_idx = d_in[5];
    const void*  neigh_idx= d_in[6];

    const int N = in_sizes[5];
    const int S = in_sizes[6] / N;

    cudaFuncSetAttribute(gemm_tc_kernel,
                         cudaFuncAttributeMaxDynamicSharedMemorySize, GEMM_SMEM);

    detect_idx_kernel<<<1, 256>>>((const unsigned int*)self_idx, N);
    wconv_kernel<<<(DD * KK / 4) / 256, 256>>>(W);
    agg_kernel<<<N, 128>>>((const float4*)features, self_idx, neigh_idx, N, S);

    dim3 ggrid(DD / 128, (N + 127) / 128);
    gemm_tc_kernel<<<ggrid, 256, GEMM_SMEM>>>(b, N);

    const int nblk = (N + 127) / 128;
    finalize_stats<<<64, 256>>>(gamma, beta, N, nblk);

    bn_l2_kernel<<<N, 128>>>((float4*)d_out, N);
}

// round 7
// speedup vs baseline: 1.6931x; 1.2514x over previous
#include <cuda_runtime.h>
#include <cuda_fp16.h>
#include <cstdint>
#include <cstddef>

// ---------------------------------------------------------------------------
// SAGEConv: gather+mean-agg -> concat -> Linear(1024->512)+ReLU -> BatchNorm
//           -> row L2 normalize.
// R7: fp16 feature table (half gather traffic), single-pass fp16 HMMA GEMM
//     (A and W both fp16, fp32 accumulate), BN stats fused in GEMM epilogue.
// ---------------------------------------------------------------------------

#define DD      512
#define KK      1024
#define NMAX    20000
#define NTOT    40000
#define NPAD    20096           // 157 * 128
#define MAXBLK  640

// ------------------------- device scratch (no mallocs) ---------------------
__device__ __align__(16) __half g_F16[(size_t)NTOT * DD];   // fp16 features 41 MB
__device__ __align__(16) __half g_A  [(size_t)NPAD * KK];   // concat fp16   41 MB
__device__ __align__(16) __half g_W16[(size_t)DD * KK];     // fp16 W         1 MB
__device__ __align__(16) float g_H[(size_t)NMAX * DD];      // post-ReLU     41 MB
__device__ float g_psum  [MAXBLK * DD];
__device__ float g_psumsq[MAXBLK * DD];
__device__ __align__(16) float g_scale[DD];
__device__ __align__(16) float g_shift[DD];
__device__ int   g_idx_is64;

// ------------------------- helpers -----------------------------------------
__device__ __forceinline__ uint32_t smem_u32(const void* p) {
    uint32_t a;
    asm("{ .reg .u64 t; cvta.to.shared.u64 t, %1; cvt.u32.u64 %0, t; }"
        : "=r"(a) : "l"(p));
    return a;
}
__device__ __forceinline__ void cpasync16(uint32_t dst, const void* src) {
    asm volatile("cp.async.cg.shared.global [%0], [%1], 16;"
                 :: "r"(dst), "l"(src) : "memory");
}
__device__ __forceinline__ void cp_commit() {
    asm volatile("cp.async.commit_group;" ::: "memory");
}
__device__ __forceinline__ void ldsm4(uint32_t& r0, uint32_t& r1,
                                      uint32_t& r2, uint32_t& r3, uint32_t a) {
    asm volatile("ldmatrix.sync.aligned.m8n8.x4.shared.b16 {%0,%1,%2,%3}, [%4];"
                 : "=r"(r0), "=r"(r1), "=r"(r2), "=r"(r3) : "r"(a));
}
__device__ __forceinline__ void mma16816(float* d, const uint32_t* a,
                                         const uint32_t* b) {
    asm volatile(
        "mma.sync.aligned.m16n8k16.row.col.f32.f16.f16.f32 "
        "{%0,%1,%2,%3}, {%4,%5,%6,%7}, {%8,%9}, {%0,%1,%2,%3};"
        : "+f"(d[0]), "+f"(d[1]), "+f"(d[2]), "+f"(d[3])
        : "r"(a[0]), "r"(a[1]), "r"(a[2]), "r"(a[3]), "r"(b[0]), "r"(b[1]));
}
__device__ __forceinline__ uint32_t packh2(float x0, float x1) {
    __half2 h = __floats2half2_rn(x0, x1);
    return *reinterpret_cast<uint32_t*>(&h);
}

// ------------------------- index dtype detection ---------------------------
__global__ void detect_idx_kernel(const unsigned int* __restrict__ p, int n) {
    __shared__ unsigned int red[256];
    unsigned int acc = 0;
    for (int i = threadIdx.x; i < n; i += blockDim.x)
        if (i & 1) acc |= p[i];
    red[threadIdx.x] = acc;
    __syncthreads();
    for (int s = 128; s > 0; s >>= 1) {
        if (threadIdx.x < s) red[threadIdx.x] |= red[threadIdx.x + s];
        __syncthreads();
    }
    if (threadIdx.x == 0) g_idx_is64 = (red[0] == 0u) ? 1 : 0;
}
__device__ __forceinline__ long long load_idx(const void* p, size_t i, int is64) {
    if (is64) return ((const long long*)p)[i];
    return (long long)((const int*)p)[i];
}

// ------------------------- kernel 0: features f32 -> fp16 ------------------
__global__ __launch_bounds__(256)
void fconv_kernel(const float4* __restrict__ feat4, int total4) {
    const int i = blockIdx.x * 256 + threadIdx.x;
    if (i >= total4) return;
    const float4 v = feat4[i];
    uint2 o;
    o.x = packh2(v.x, v.y);
    o.y = packh2(v.z, v.w);
    ((uint2*)g_F16)[i] = o;
}

// ------------------------- kernel 1: gather(fp16) + mean agg ---------------
__global__ __launch_bounds__(128)
void agg_kernel(const void* __restrict__ self_idx,
                const void* __restrict__ neigh_idx,
                int N, int S) {
    const int n = blockIdx.x;
    const int t = threadIdx.x;          // owns halfs 4t..4t+3
    __shared__ long long sidx[40];
    const int is64 = g_idx_is64;
    if (t == 0) sidx[S] = load_idx(self_idx, n, is64);
    if (t < S)  sidx[t] = load_idx(neigh_idx, (size_t)n * S + t, is64);
    __syncthreads();

    const uint2* F2 = reinterpret_cast<const uint2*>(g_F16);
    uint2* A2 = reinterpret_cast<uint2*>(g_A);

    // self half (cols 0..511): straight fp16 copy
    A2[(size_t)n * 256 + t] = F2[(size_t)sidx[S] * 128 + t];

    // aggregated half (cols 512..1023): fp32 accumulate of fp16 reads
    float a0 = 0.f, a1 = 0.f, a2 = 0.f, a3 = 0.f;
    for (int s = 0; s < S; ++s) {
        uint2 v = F2[(size_t)sidx[s] * 128 + t];
        float2 f0 = __half22float2(*reinterpret_cast<__half2*>(&v.x));
        float2 f1 = __half22float2(*reinterpret_cast<__half2*>(&v.y));
        a0 += f0.x; a1 += f0.y; a2 += f1.x; a3 += f1.y;
    }
    const float inv = 1.0f / (float)S;
    uint2 o;
    o.x = packh2(a0 * inv, a1 * inv);
    o.y = packh2(a2 * inv, a3 * inv);
    A2[(size_t)n * 256 + 128 + t] = o;
}

// ------------------------- kernel 1b: W f32 -> fp16 ------------------------
__global__ __launch_bounds__(256)
void wconv_kernel(const float* __restrict__ W) {
    const int i = blockIdx.x * 256 + threadIdx.x;    // over DD*KK/4
    const float4 v = *(const float4*)(W + (size_t)i * 4);
    uint2 o;
    o.x = packh2(v.x, v.y);
    o.y = packh2(v.z, v.w);
    ((uint2*)g_W16)[i] = o;
}

// ------------------------- kernel 2: HMMA GEMM + bias + ReLU + BN partials -
// H[128x128 tile] = A[128,1024] * W[128-slice,1024]^T, single fp16 pass.
// 2 variants (A, W) of [128 rows][32 k] fp16, row stride 80B; 3 stages,
// one __syncthreads per chunk.
#define SASTRIDE 80
#define VARB     10240                    // 128*80 per variant
#define STAGEB   (2 * VARB)               // 20480
#define NSTAGE   3
#define HDRB     1024
#define GEMM_SMEM (HDRB + NSTAGE * STAGEB)   // 62464 -> 2 CTAs/SM

__global__ __launch_bounds__(256, 2)
void gemm_tc_kernel(const float* __restrict__ bias, int M) {
    extern __shared__ char smem[];
    const uint32_t sb = smem_u32(smem);
    const int tid  = threadIdx.x;
    const int wid  = tid >> 5;
    const int lane = tid & 31;
    const int wm   = wid >> 2;            // 0..1  (64 rows each)
    const int wn   = wid & 3;             // 0..3  (32 cols each)
    const int m0 = blockIdx.y * 128;
    const int n0 = blockIdx.x * 128;

    float* bsm = (float*)smem;            // bias cache [128]
    if (tid < 128) bsm[tid] = bias[n0 + tid];

    const uint32_t aOff = (uint32_t)((lane & 15) * SASTRIDE + (lane >> 4) * 16);
    const uint32_t bOff = (uint32_t)(((lane & 7) + ((lane >> 4) << 3)) * SASTRIDE
                                     + (((lane >> 3) & 1) << 4));

    const char* pA = (const char*)g_A;
    const char* pW = (const char*)g_W16;

    auto load_chunk = [&](int stage, int kc) {
        const uint32_t base = sb + HDRB + stage * STAGEB;
        #pragma unroll
        for (int i = 0; i < 2; ++i) {
            const int idx = tid + (i << 8);
            const int r = idx >> 2, c = idx & 3;
            const uint32_t dst = base + (uint32_t)(r * SASTRIDE + c * 16);
            const size_t sa  = ((size_t)(m0 + r) << 11) + (size_t)(kc * 64 + c * 16);
            const size_t sbo = ((size_t)(n0 + r) << 11) + (size_t)(kc * 64 + c * 16);
            cpasync16(dst,        pA + sa);
            cpasync16(dst + VARB, pW + sbo);
        }
        cp_commit();
    };

    float acc[4][4][4];
    #pragma unroll
    for (int i = 0; i < 4; ++i)
        #pragma unroll
        for (int j = 0; j < 4; ++j)
            #pragma unroll
            for (int q = 0; q < 4; ++q) acc[i][j][q] = 0.f;

    load_chunk(0, 0);
    load_chunk(1, 1);

    const int NKC = KK / 32;              // 32 chunks
    for (int kc = 0; kc < NKC; ++kc) {
        asm volatile("cp.async.wait_group 1;" ::: "memory");
        __syncthreads();

        if (kc + 2 < NKC) load_chunk((kc + 2) % 3, kc + 2);
        else              cp_commit();

        const uint32_t st = sb + HDRB + (kc % 3) * STAGEB;
        const uint32_t bufA = st;
        const uint32_t bufB = st + VARB;

        #pragma unroll
        for (int k16 = 0; k16 < 2; ++k16) {
            const uint32_t kb = (uint32_t)(k16 * 32);
            uint32_t a[4][4], bfr[2][4];
            #pragma unroll
            for (int j2 = 0; j2 < 2; ++j2) {
                const uint32_t ro = (uint32_t)((wn * 32 + j2 * 16) * SASTRIDE) + kb;
                ldsm4(bfr[j2][0], bfr[j2][1], bfr[j2][2], bfr[j2][3], bufB + ro + bOff);
            }
            #pragma unroll
            for (int im = 0; im < 4; ++im) {
                const uint32_t ro = (uint32_t)((wm * 64 + im * 16) * SASTRIDE) + kb;
                ldsm4(a[im][0], a[im][1], a[im][2], a[im][3], bufA + ro + aOff);
            }
            #pragma unroll
            for (int im = 0; im < 4; ++im)
                #pragma unroll
                for (int jn = 0; jn < 4; ++jn)
                    mma16816(acc[im][jn], a[im], &bfr[jn >> 1][(jn & 1) * 2]);
        }
    }

    // ---- epilogue: bias + relu -> g_H, plus BN partial sums (fused) ----
    __syncthreads();                       // done with pipeline smem; reuse it
    float* psum = (float*)(smem + HDRB);            // [128 cols][16 slots]
    float* psq  = (float*)(smem + HDRB + 8192);
    const int g    = lane >> 2;
    const int tq   = lane & 3;
    const int slot = wm * 8 + g;

    #pragma unroll
    for (int jn = 0; jn < 4; ++jn) {
        const int colL = wn * 32 + jn * 8 + tq * 2;
        const float b0 = bsm[colL], b1 = bsm[colL + 1];
        float s0 = 0.f, s1 = 0.f, q0 = 0.f, q1 = 0.f;
        #pragma unroll
        for (int im = 0; im < 4; ++im) {
            const int row0 = m0 + wm * 64 + im * 16 + g;
            float v0 = acc[im][jn][0] + b0;
            float v1 = acc[im][jn][1] + b1;
            float v2 = acc[im][jn][2] + b0;
            float v3 = acc[im][jn][3] + b1;
            v0 = v0 > 0.f ? v0 : 0.f;
            v1 = v1 > 0.f ? v1 : 0.f;
            v2 = v2 > 0.f ? v2 : 0.f;
            v3 = v3 > 0.f ? v3 : 0.f;
            const int col = n0 + colL;
            if (row0 < M) {
                *(float2*)(g_H + (size_t)row0 * DD + col) = make_float2(v0, v1);
                s0 += v0; s1 += v1; q0 += v0 * v0; q1 += v1 * v1;
            }
            if (row0 + 8 < M) {
                *(float2*)(g_H + (size_t)(row0 + 8) * DD + col) = make_float2(v2, v3);
                s0 += v2; s1 += v3; q0 += v2 * v2; q1 += v3 * v3;
            }
        }
        psum[colL * 16 + slot]       = s0;
        psum[(colL + 1) * 16 + slot] = s1;
        psq [colL * 16 + slot]       = q0;
        psq [(colL + 1) * 16 + slot] = q1;
    }
    __syncthreads();

    // deterministic slot reduction: 256 threads -> 128 cols x {sum, sumsq}
    {
        const int col = tid & 127;
        const float* src = (tid & 128) ? psq : psum;
        float s = 0.f;
        #pragma unroll
        for (int k = 0; k < 16; ++k) s += src[col * 16 + k];
        float* dstg = (tid & 128) ? g_psumsq : g_psum;
        dstg[blockIdx.y * DD + n0 + col] = s;
    }
}

// ------------------------- BN finalize -------------------------------------
__global__ __launch_bounds__(256)
void finalize_stats(const float* __restrict__ gamma,
                    const float* __restrict__ beta, int M, int nblk) {
    const int col  = blockIdx.x * 8 + (threadIdx.x >> 5);
    const int lane = threadIdx.x & 31;
    float s = 0.f, q = 0.f;
    for (int i = lane; i < nblk; i += 32) {
        s += g_psum  [i * DD + col];
        q += g_psumsq[i * DD + col];
    }
    #pragma unroll
    for (int o = 16; o > 0; o >>= 1) {
        s += __shfl_xor_sync(0xffffffffu, s, o);
        q += __shfl_xor_sync(0xffffffffu, q, o);
    }
    if (lane == 0) {
        const float invM = 1.0f / (float)M;
        const float mean = s * invM;
        const float var  = q * invM - mean * mean;
        const float rstd = rsqrtf(var + 1e-5f);
        const float sc = rstd * gamma[col];
        g_scale[col] = sc;
        g_shift[col] = beta[col] - mean * sc;
    }
}

// ------------------------- kernel 4: BN apply + row L2 normalize -----------
__global__ __launch_bounds__(128)
void bn_l2_kernel(float4* __restrict__ out4, int M) {
    const int n = blockIdx.x;
    const int t = threadIdx.x;
    const float4* H4  = reinterpret_cast<const float4*>(g_H);
    const float4* sc4 = reinterpret_cast<const float4*>(g_scale);
    const float4* sh4 = reinterpret_cast<const float4*>(g_shift);

    float4 h  = H4[(size_t)n * 128 + t];
    float4 sc = sc4[t];
    float4 sh = sh4[t];
    float4 y;
    y.x = h.x * sc.x + sh.x;
    y.y = h.y * sc.y + sh.y;
    y.z = h.z * sc.z + sh.z;
    y.w = h.w * sc.w + sh.w;

    float ss = y.x * y.x + y.y * y.y + y.z * y.z + y.w * y.w;
    #pragma unroll
    for (int o = 16; o > 0; o >>= 1)
        ss += __shfl_xor_sync(0xffffffffu, ss, o);

    __shared__ float ws[4];
    if ((t & 31) == 0) ws[t >> 5] = ss;
    __syncthreads();
    const float tot = ws[0] + ws[1] + ws[2] + ws[3];
    const float inv = 1.0f / (sqrtf(tot) + 1e-6f);

    y.x *= inv; y.y *= inv; y.z *= inv; y.w *= inv;
    out4[(size_t)n * 128 + t] = y;
}

// ------------------------- launcher ----------------------------------------
extern "C" void kernel_launch(void* const* d_in, const int* in_sizes, int n_in,
                              void* d_out, int out_size) {
    const float* features = (const float*)d_in[0];
    const float* W        = (const float*)d_in[1];
    const float* b        = (const float*)d_in[2];
    const float* gamma    = (const float*)d_in[3];
    const float* beta     = (const float*)d_in[4];
    const void*  self_idx = d_in[5];
    const void*  neigh_idx= d_in[6];

    const int N = in_sizes[5];
    const int S = in_sizes[6] / N;
    const int total4 = in_sizes[0] / 4;   // feature f32 count / 4

    cudaFuncSetAttribute(gemm_tc_kernel,
                         cudaFuncAttributeMaxDynamicSharedMemorySize, GEMM_SMEM);

    detect_idx_kernel<<<1, 256>>>((const unsigned int*)self_idx, N);
    fconv_kernel<<<(total4 + 255) / 256, 256>>>((const float4*)features, total4);
    wconv_kernel<<<(DD * KK / 4) / 256, 256>>>(W);
    agg_kernel<<<N, 128>>>(self_idx, neigh_idx, N, S);

    dim3 ggrid(DD / 128, (N + 127) / 128);
    gemm_tc_kernel<<<ggrid, 256, GEMM_SMEM>>>(b, N);

    const int nblk = (N + 127) / 128;
    finalize_stats<<<64, 256>>>(gamma, beta, N, nblk);

    bn_l2_kernel<<<N, 128>>>((float4*)d_out, N);
}

// round 8
// speedup vs baseline: 1.7495x; 1.0333x over previous
#include <cuda_runtime.h>
#include <cuda_fp16.h>
#include <cstdint>
#include <cstddef>

// ---------------------------------------------------------------------------
// SAGEConv: gather+mean-agg -> concat -> Linear(1024->512)+ReLU -> BatchNorm
//           -> row L2 normalize.
// R8: agg_kernel with 16B loads + 32-bit addressing (was issue/ALU-bound);
//     single-pass fp16 HMMA GEMM, BN stats fused in GEMM epilogue.
// ---------------------------------------------------------------------------

#define DD      512
#define KK      1024
#define NMAX    20000
#define NTOT    40000
#define NPAD    20096           // 157 * 128
#define MAXBLK  640

// ------------------------- device scratch (no mallocs) ---------------------
__device__ __align__(16) __half g_F16[(size_t)NTOT * DD];   // fp16 features 41 MB
__device__ __align__(16) __half g_A  [(size_t)NPAD * KK];   // concat fp16   41 MB
__device__ __align__(16) __half g_W16[(size_t)DD * KK];     // fp16 W         1 MB
__device__ __align__(16) float g_H[(size_t)NMAX * DD];      // post-ReLU     41 MB
__device__ float g_psum  [MAXBLK * DD];
__device__ float g_psumsq[MAXBLK * DD];
__device__ __align__(16) float g_scale[DD];
__device__ __align__(16) float g_shift[DD];
__device__ int   g_idx_is64;

// ------------------------- helpers -----------------------------------------
__device__ __forceinline__ uint32_t smem_u32(const void* p) {
    uint32_t a;
    asm("{ .reg .u64 t; cvta.to.shared.u64 t, %1; cvt.u32.u64 %0, t; }"
        : "=r"(a) : "l"(p));
    return a;
}
__device__ __forceinline__ void cpasync16(uint32_t dst, const void* src) {
    asm volatile("cp.async.cg.shared.global [%0], [%1], 16;"
                 :: "r"(dst), "l"(src) : "memory");
}
__device__ __forceinline__ void cp_commit() {
    asm volatile("cp.async.commit_group;" ::: "memory");
}
__device__ __forceinline__ void ldsm4(uint32_t& r0, uint32_t& r1,
                                      uint32_t& r2, uint32_t& r3, uint32_t a) {
    asm volatile("ldmatrix.sync.aligned.m8n8.x4.shared.b16 {%0,%1,%2,%3}, [%4];"
                 : "=r"(r0), "=r"(r1), "=r"(r2), "=r"(r3) : "r"(a));
}
__device__ __forceinline__ void mma16816(float* d, const uint32_t* a,
                                         const uint32_t* b) {
    asm volatile(
        "mma.sync.aligned.m16n8k16.row.col.f32.f16.f16.f32 "
        "{%0,%1,%2,%3}, {%4,%5,%6,%7}, {%8,%9}, {%0,%1,%2,%3};"
        : "+f"(d[0]), "+f"(d[1]), "+f"(d[2]), "+f"(d[3])
        : "r"(a[0]), "r"(a[1]), "r"(a[2]), "r"(a[3]), "r"(b[0]), "r"(b[1]));
}
__device__ __forceinline__ uint32_t packh2(float x0, float x1) {
    __half2 h = __floats2half2_rn(x0, x1);
    return *reinterpret_cast<uint32_t*>(&h);
}

// ------------------------- index dtype detection ---------------------------
__global__ void detect_idx_kernel(const unsigned int* __restrict__ p, int n) {
    __shared__ unsigned int red[256];
    unsigned int acc = 0;
    for (int i = threadIdx.x; i < n; i += blockDim.x)
        if (i & 1) acc |= p[i];
    red[threadIdx.x] = acc;
    __syncthreads();
    for (int s = 128; s > 0; s >>= 1) {
        if (threadIdx.x < s) red[threadIdx.x] |= red[threadIdx.x + s];
        __syncthreads();
    }
    if (threadIdx.x == 0) g_idx_is64 = (red[0] == 0u) ? 1 : 0;
}
__device__ __forceinline__ long long load_idx(const void* p, size_t i, int is64) {
    if (is64) return ((const long long*)p)[i];
    return (long long)((const int*)p)[i];
}

// ------------------------- kernel 0: features f32 -> fp16 ------------------
// 32B of f32 in, 16B of fp16 out per thread
__global__ __launch_bounds__(256)
void fconv_kernel(const float4* __restrict__ feat4, int total8) {
    const int i = blockIdx.x * 256 + threadIdx.x;
    if (i >= total8) return;
    const float4 v0 = feat4[2 * i];
    const float4 v1 = feat4[2 * i + 1];
    uint4 o;
    o.x = packh2(v0.x, v0.y);
    o.y = packh2(v0.z, v0.w);
    o.z = packh2(v1.x, v1.y);
    o.w = packh2(v1.z, v1.w);
    ((uint4*)g_F16)[i] = o;
}

// ------------------------- kernel 1: gather(fp16) + mean agg ---------------
// 256 threads = 4 rows x 64 lanes; each lane owns 16B (8 halves) of the row.
// 32-bit byte offsets into the 41 MB fp16 table: idx<<10 | lane<<4.
__global__ __launch_bounds__(256)
void agg_kernel(const void* __restrict__ self_idx,
                const void* __restrict__ neigh_idx,
                int N, int S) {
    const int rg   = threadIdx.x >> 6;    // 0..3 row-in-block
    const int lane = threadIdx.x & 63;    // 16B column
    const int n    = blockIdx.x * 4 + rg;
    __shared__ int sidx[4][33];           // [row][S neighbors + self at S]
    const int is64 = g_idx_is64;

    for (int i = threadIdx.x; i < 4 * S; i += 256) {
        const int r = i / S, s = i - r * S;
        const int row = blockIdx.x * 4 + r;
        if (row < N)
            sidx[r][s] = (int)load_idx(neigh_idx, (size_t)row * S + s, is64);
    }
    if (threadIdx.x < 4) {
        const int row = blockIdx.x * 4 + threadIdx.x;
        if (row < N)
            sidx[threadIdx.x][S] = (int)load_idx(self_idx, row, is64);
    }
    __syncthreads();
    if (n >= N) return;

    const char* F = (const char*)g_F16;
    const uint32_t lo = (uint32_t)(lane << 4);
    uint4* A4 = reinterpret_cast<uint4*>(g_A);

    // self half (cols 0..511): straight 16B copy
    A4[(size_t)n * 128 + lane] =
        *(const uint4*)(F + (((uint32_t)sidx[rg][S] << 10) | lo));

    // aggregated half: fp32 accumulate of fp16 reads
    float a0 = 0.f, a1 = 0.f, a2 = 0.f, a3 = 0.f;
    float a4 = 0.f, a5 = 0.f, a6 = 0.f, a7 = 0.f;
    #pragma unroll 5
    for (int s = 0; s < S; ++s) {
        const uint4 v = *(const uint4*)(F + (((uint32_t)sidx[rg][s] << 10) | lo));
        float2 f0 = __half22float2(*reinterpret_cast<const __half2*>(&v.x));
        float2 f1 = __half22float2(*reinterpret_cast<const __half2*>(&v.y));
        float2 f2 = __half22float2(*reinterpret_cast<const __half2*>(&v.z));
        float2 f3 = __half22float2(*reinterpret_cast<const __half2*>(&v.w));
        a0 += f0.x; a1 += f0.y; a2 += f1.x; a3 += f1.y;
        a4 += f2.x; a5 += f2.y; a6 += f3.x; a7 += f3.y;
    }
    const float inv = 1.0f / (float)S;
    uint4 o;
    o.x = packh2(a0 * inv, a1 * inv);
    o.y = packh2(a2 * inv, a3 * inv);
    o.z = packh2(a4 * inv, a5 * inv);
    o.w = packh2(a6 * inv, a7 * inv);
    A4[(size_t)n * 128 + 64 + lane] = o;
}

// ------------------------- kernel 1b: W f32 -> fp16 ------------------------
__global__ __launch_bounds__(256)
void wconv_kernel(const float* __restrict__ W) {
    const int i = blockIdx.x * 256 + threadIdx.x;    // over DD*KK/8
    const float4 v0 = *(const float4*)(W + (size_t)i * 8);
    const float4 v1 = *(const float4*)(W + (size_t)i * 8 + 4);
    uint4 o;
    o.x = packh2(v0.x, v0.y);
    o.y = packh2(v0.z, v0.w);
    o.z = packh2(v1.x, v1.y);
    o.w = packh2(v1.z, v1.w);
    ((uint4*)g_W16)[i] = o;
}

// ------------------------- kernel 2: HMMA GEMM + bias + ReLU + BN partials -
#define SASTRIDE 80
#define VARB     10240                    // 128*80 per variant
#define STAGEB   (2 * VARB)               // 20480
#define NSTAGE   3
#define HDRB     1024
#define GEMM_SMEM (HDRB + NSTAGE * STAGEB)   // 62464 -> 2 CTAs/SM

__global__ __launch_bounds__(256, 2)
void gemm_tc_kernel(const float* __restrict__ bias, int M) {
    extern __shared__ char smem[];
    const uint32_t sb = smem_u32(smem);
    const int tid  = threadIdx.x;
    const int wid  = tid >> 5;
    const int lane = tid & 31;
    const int wm   = wid >> 2;
    const int wn   = wid & 3;
    const int m0 = blockIdx.y * 128;
    const int n0 = blockIdx.x * 128;

    float* bsm = (float*)smem;
    if (tid < 128) bsm[tid] = bias[n0 + tid];

    const uint32_t aOff = (uint32_t)((lane & 15) * SASTRIDE + (lane >> 4) * 16);
    const uint32_t bOff = (uint32_t)(((lane & 7) + ((lane >> 4) << 3)) * SASTRIDE
                                     + (((lane >> 3) & 1) << 4));

    const char* pA = (const char*)g_A;
    const char* pW = (const char*)g_W16;

    auto load_chunk = [&](int stage, int kc) {
        const uint32_t base = sb + HDRB + stage * STAGEB;
        #pragma unroll
        for (int i = 0; i < 2; ++i) {
            const int idx = tid + (i << 8);
            const int r = idx >> 2, c = idx & 3;
            const uint32_t dst = base + (uint32_t)(r * SASTRIDE + c * 16);
            const size_t sa  = ((size_t)(m0 + r) << 11) + (size_t)(kc * 64 + c * 16);
            const size_t sbo = ((size_t)(n0 + r) << 11) + (size_t)(kc * 64 + c * 16);
            cpasync16(dst,        pA + sa);
            cpasync16(dst + VARB, pW + sbo);
        }
        cp_commit();
    };

    float acc[4][4][4];
    #pragma unroll
    for (int i = 0; i < 4; ++i)
        #pragma unroll
        for (int j = 0; j < 4; ++j)
            #pragma unroll
            for (int q = 0; q < 4; ++q) acc[i][j][q] = 0.f;

    load_chunk(0, 0);
    load_chunk(1, 1);

    const int NKC = KK / 32;
    for (int kc = 0; kc < NKC; ++kc) {
        asm volatile("cp.async.wait_group 1;" ::: "memory");
        __syncthreads();

        if (kc + 2 < NKC) load_chunk((kc + 2) % 3, kc + 2);
        else              cp_commit();

        const uint32_t st = sb + HDRB + (kc % 3) * STAGEB;
        const uint32_t bufA = st;
        const uint32_t bufB = st + VARB;

        #pragma unroll
        for (int k16 = 0; k16 < 2; ++k16) {
            const uint32_t kb = (uint32_t)(k16 * 32);
            uint32_t a[4][4], bfr[2][4];
            #pragma unroll
            for (int j2 = 0; j2 < 2; ++j2) {
                const uint32_t ro = (uint32_t)((wn * 32 + j2 * 16) * SASTRIDE) + kb;
                ldsm4(bfr[j2][0], bfr[j2][1], bfr[j2][2], bfr[j2][3], bufB + ro + bOff);
            }
            #pragma unroll
            for (int im = 0; im < 4; ++im) {
                const uint32_t ro = (uint32_t)((wm * 64 + im * 16) * SASTRIDE) + kb;
                ldsm4(a[im][0], a[im][1], a[im][2], a[im][3], bufA + ro + aOff);
            }
            #pragma unroll
            for (int im = 0; im < 4; ++im)
                #pragma unroll
                for (int jn = 0; jn < 4; ++jn)
                    mma16816(acc[im][jn], a[im], &bfr[jn >> 1][(jn & 1) * 2]);
        }
    }

    // ---- epilogue: bias + relu -> g_H, plus BN partial sums (fused) ----
    __syncthreads();
    float* psum = (float*)(smem + HDRB);            // [128 cols][16 slots]
    float* psq  = (float*)(smem + HDRB + 8192);
    const int g    = lane >> 2;
    const int tq   = lane & 3;
    const int slot = wm * 8 + g;

    #pragma unroll
    for (int jn = 0; jn < 4; ++jn) {
        const int colL = wn * 32 + jn * 8 + tq * 2;
        const float b0 = bsm[colL], b1 = bsm[colL + 1];
        float s0 = 0.f, s1 = 0.f, q0 = 0.f, q1 = 0.f;
        #pragma unroll
        for (int im = 0; im < 4; ++im) {
            const int row0 = m0 + wm * 64 + im * 16 + g;
            float v0 = acc[im][jn][0] + b0;
            float v1 = acc[im][jn][1] + b1;
            float v2 = acc[im][jn][2] + b0;
            float v3 = acc[im][jn][3] + b1;
            v0 = v0 > 0.f ? v0 : 0.f;
            v1 = v1 > 0.f ? v1 : 0.f;
            v2 = v2 > 0.f ? v2 : 0.f;
            v3 = v3 > 0.f ? v3 : 0.f;
            const int col = n0 + colL;
            if (row0 < M) {
                *(float2*)(g_H + (size_t)row0 * DD + col) = make_float2(v0, v1);
                s0 += v0; s1 += v1; q0 += v0 * v0; q1 += v1 * v1;
            }
            if (row0 + 8 < M) {
                *(float2*)(g_H + (size_t)(row0 + 8) * DD + col) = make_float2(v2, v3);
                s0 += v2; s1 += v3; q0 += v2 * v2; q1 += v3 * v3;
            }
        }
        psum[colL * 16 + slot]       = s0;
        psum[(colL + 1) * 16 + slot] = s1;
        psq [colL * 16 + slot]       = q0;
        psq [(colL + 1) * 16 + slot] = q1;
    }
    __syncthreads();

    {
        const int col = tid & 127;
        const float* src = (tid & 128) ? psq : psum;
        float s = 0.f;
        #pragma unroll
        for (int k = 0; k < 16; ++k) s += src[col * 16 + k];
        float* dstg = (tid & 128) ? g_psumsq : g_psum;
        dstg[blockIdx.y * DD + n0 + col] = s;
    }
}

// ------------------------- BN finalize -------------------------------------
__global__ __launch_bounds__(256)
void finalize_stats(const float* __restrict__ gamma,
                    const float* __restrict__ beta, int M, int nblk) {
    const int col  = blockIdx.x * 8 + (threadIdx.x >> 5);
    const int lane = threadIdx.x & 31;
    float s = 0.f, q = 0.f;
    for (int i = lane; i < nblk; i += 32) {
        s += g_psum  [i * DD + col];
        q += g_psumsq[i * DD + col];
    }
    #pragma unroll
    for (int o = 16; o > 0; o >>= 1) {
        s += __shfl_xor_sync(0xffffffffu, s, o);
        q += __shfl_xor_sync(0xffffffffu, q, o);
    }
    if (lane == 0) {
        const float invM = 1.0f / (float)M;
        const float mean = s * invM;
        const float var  = q * invM - mean * mean;
        const float rstd = rsqrtf(var + 1e-5f);
        const float sc = rstd * gamma[col];
        g_scale[col] = sc;
        g_shift[col] = beta[col] - mean * sc;
    }
}

// ------------------------- kernel 4: BN apply + row L2 normalize -----------
__global__ __launch_bounds__(128)
void bn_l2_kernel(float4* __restrict__ out4, int M) {
    const int n = blockIdx.x;
    const int t = threadIdx.x;
    const float4* H4  = reinterpret_cast<const float4*>(g_H);
    const float4* sc4 = reinterpret_cast<const float4*>(g_scale);
    const float4* sh4 = reinterpret_cast<const float4*>(g_shift);

    float4 h  = H4[(size_t)n * 128 + t];
    float4 sc = sc4[t];
    float4 sh = sh4[t];
    float4 y;
    y.x = h.x * sc.x + sh.x;
    y.y = h.y * sc.y + sh.y;
    y.z = h.z * sc.z + sh.z;
    y.w = h.w * sc.w + sh.w;

    float ss = y.x * y.x + y.y * y.y + y.z * y.z + y.w * y.w;
    #pragma unroll
    for (int o = 16; o > 0; o >>= 1)
        ss += __shfl_xor_sync(0xffffffffu, ss, o);

    __shared__ float ws[4];
    if ((t & 31) == 0) ws[t >> 5] = ss;
    __syncthreads();
    const float tot = ws[0] + ws[1] + ws[2] + ws[3];
    const float inv = 1.0f / (sqrtf(tot) + 1e-6f);

    y.x *= inv; y.y *= inv; y.z *= inv; y.w *= inv;
    out4[(size_t)n * 128 + t] = y;
}

// ------------------------- launcher ----------------------------------------
extern "C" void kernel_launch(void* const* d_in, const int* in_sizes, int n_in,
                              void* d_out, int out_size) {
    const float* features = (const float*)d_in[0];
    const float* W        = (const float*)d_in[1];
    const float* b        = (const float*)d_in[2];
    const float* gamma    = (const float*)d_in[3];
    const float* beta     = (const float*)d_in[4];
    const void*  self_idx = d_in[5];
    const void*  neigh_idx= d_in[6];

    const int N = in_sizes[5];
    const int S = in_sizes[6] / N;
    const int total8 = in_sizes[0] / 8;

    cudaFuncSetAttribute(gemm_tc_kernel,
                         cudaFuncAttributeMaxDynamicSharedMemorySize, GEMM_SMEM);

    detect_idx_kernel<<<1, 256>>>((const unsigned int*)self_idx, N);
    fconv_kernel<<<(total8 + 255) / 256, 256>>>((const float4*)features, total8);
    wconv_kernel<<<(DD * KK / 8) / 256, 256>>>(W);
    agg_kernel<<<(N + 3) / 4, 256>>>(self_idx, neigh_idx, N, S);

    dim3 ggrid(DD / 128, (N + 127) / 128);
    gemm_tc_kernel<<<ggrid, 256, GEMM_SMEM>>>(b, N);

    const int nblk = (N + 127) / 128;
    finalize_stats<<<64, 256>>>(gamma, beta, N, nblk);

    bn_l2_kernel<<<N, 128>>>((float4*)d_out, N);
}